// round 8
// baseline (speedup 1.0000x reference)
#include <cuda_runtime.h>
#include <cuda_bf16.h>
#include <cstdint>

typedef unsigned int u32;
typedef unsigned long long u64;

#define NB    1024
#define DIN   784
#define DINP8 896         // padded K per plane: 7 * 128
#define NH1   2048
#define NH2   10
#define NK    10
#define NU    2832        // DIN + NH1
#define NL    128
#define TSTEPS 20
#define NCHUNK 21         // 3 planes * 7 chunks of K=128
#define ABUF  8192        // 64 rows * 128B
#define BBUF  16384       // 128 rows * 128B
#define DSMEM_SZ (3 * (ABUF + BBUF))   // 73728

// ---------------- device state (no allocations allowed) ----------------
__device__ __align__(16) signed char g_xq[NB * DINP8];            // spikes int8 (0/1)
__device__ __align__(16) signed char g_wq[3ll * NH1 * DINP8];     // W1 3-plane int8 split
__device__ int   g_smaxi;     // max |W1| as float bits
__device__ float g_sc[3];     // plane scales s1, s2, s3
__device__ float g_h1m[NB * NH1];
__device__ float g_h1s[NB * NH1];
__device__ float g_h2m[NB * NH2];
__device__ float g_h2s[NB * NH2];
__device__ float g_h2sum[NB * NH2];
__device__ float g_xs[DIN];
__device__ float g_hs[NH1];
__device__ float g_v1[NU];
__device__ float g_v2[NU];
__device__ float g_scal[3];   // a1, a2, cs

// ---------------- threefry2x32 (20 rounds), bit-exact vs JAX ----------------
__device__ __forceinline__ void threefry(unsigned k0, unsigned k1,
                                         unsigned x0, unsigned x1,
                                         unsigned& o0, unsigned& o1) {
    unsigned k2 = k0 ^ k1 ^ 0x1BD11BDAu;
    x0 += k0; x1 += k1;
#define RO(r) x0 += x1; x1 = __funnelshift_l(x1, x1, (r)); x1 ^= x0;
    RO(13) RO(15) RO(26) RO(6)   x0 += k1; x1 += k2 + 1u;
    RO(17) RO(29) RO(16) RO(24)  x0 += k2; x1 += k0 + 2u;
    RO(13) RO(15) RO(26) RO(6)   x0 += k0; x1 += k1 + 3u;
    RO(17) RO(29) RO(16) RO(24)  x0 += k1; x1 += k2 + 4u;
    RO(13) RO(15) RO(26) RO(6)   x0 += k2; x1 += k0 + 5u;
#undef RO
    o0 = x0; o1 = x1;
}

// ---------------- PTX wrappers ----------------
__device__ __forceinline__ void ldm4(u32 addr, u32& r0, u32& r1, u32& r2, u32& r3) {
    asm volatile("ldmatrix.sync.aligned.m8n8.x4.shared.b16 {%0,%1,%2,%3}, [%4];"
                 : "=r"(r0), "=r"(r1), "=r"(r2), "=r"(r3) : "r"(addr));
}
__device__ __forceinline__ void imma16832(int& c0, int& c1, int& c2, int& c3,
                                          u32 a0, u32 a1, u32 a2, u32 a3,
                                          u32 b0, u32 b1) {
    asm volatile("mma.sync.aligned.m16n8k32.row.col.s32.s8.s8.s32 "
                 "{%0,%1,%2,%3},{%4,%5,%6,%7},{%8,%9},{%0,%1,%2,%3};"
                 : "+r"(c0), "+r"(c1), "+r"(c2), "+r"(c3)
                 : "r"(a0), "r"(a1), "r"(a2), "r"(a3), "r"(b0), "r"(b1));
}
__device__ __forceinline__ void cpasync16(u32 dst, const void* src) {
    asm volatile("cp.async.cg.shared.global [%0], [%1], 16;" :: "r"(dst), "l"(src) : "memory");
}
__device__ __forceinline__ void cp_commit() {
    asm volatile("cp.async.commit_group;" ::: "memory");
}
__device__ __forceinline__ void cp_wait1() {
    asm volatile("cp.async.wait_group 1;" ::: "memory");
}

// ---------------- init: zero all persistent state ----------------
__global__ void k_init() {
    int stride = gridDim.x * blockDim.x;
    for (int idx = blockIdx.x * blockDim.x + threadIdx.x; idx < NB * NH1; idx += stride) {
        g_h1m[idx] = 0.f; g_h1s[idx] = 0.f;
        if (idx < NB * DINP8) g_xq[idx] = 0;
        if (idx < NB * NH2) { g_h2m[idx] = 0.f; g_h2s[idx] = 0.f; g_h2sum[idx] = 0.f; }
        if (idx < DIN) g_xs[idx] = 0.f;
        if (idx < NH1) g_hs[idx] = 0.f;
        if (idx < 3)   g_scal[idx] = 0.f;
        if (idx == 0)  g_smaxi = 0;
    }
}

// ---------------- max |W1| (float-bits atomicMax; |w| >= 0 so bits monotonic) ----
__global__ void k_smax(const float* __restrict__ W1) {
    int i = blockIdx.x * blockDim.x + threadIdx.x;
    float m = 0.f;
    for (; i < NH1 * DIN; i += gridDim.x * blockDim.x) m = fmaxf(m, fabsf(W1[i]));
    for (int o = 16; o; o >>= 1) m = fmaxf(m, __shfl_down_sync(0xffffffffu, m, o));
    if ((threadIdx.x & 31) == 0) atomicMax(&g_smaxi, __float_as_int(m));
}
__global__ void k_scale() {
    float s1 = __int_as_float(g_smaxi) / 127.f;
    g_sc[0] = s1; g_sc[1] = s1 / 252.f; g_sc[2] = s1 / (252.f * 252.f);
}

// ---------------- lossless-to-1e-8 3-way int8 split of W1 (K-padded) ----------------
__global__ void k_split(const float* __restrict__ W1) {
    long long i = blockIdx.x * blockDim.x + threadIdx.x;
    if (i >= (long long)NH1 * DINP8) return;
    int n = (int)(i / DINP8), col = (int)(i - (long long)n * DINP8);
    float w = (col < DIN) ? W1[n * DIN + col] : 0.f;
    float s1 = g_sc[0], s2 = g_sc[1], s3 = g_sc[2];
    int q1 = __float2int_rn(w / s1);  q1 = max(-127, min(127, q1));
    float r1 = fmaf(-s1, (float)q1, w);
    int q2 = __float2int_rn(r1 / s2); q2 = max(-127, min(127, q2));
    float r2 = fmaf(-s2, (float)q2, r1);
    int q3 = __float2int_rn(r2 / s3); q3 = max(-127, min(127, q3));
    g_wq[i] = (signed char)q1;
    g_wq[(long long)NH1 * DINP8 + i] = (signed char)q2;
    g_wq[2ll * NH1 * DINP8 + i] = (signed char)q3;
}

// ---------------- precompute val1/val2 over core memory ----------------
__global__ void k_val(const float* __restrict__ vec, const int* __restrict__ cnt) {
    int u = blockIdx.x * blockDim.x + threadIdx.x;
    if (u >= NU) return;
    float v1 = 0.f, v2 = 0.f;
    for (int k = 0; k < NK; k++) {
        const float* p = vec + ((size_t)k * NU + u) * NL;
        int last = -1;
        for (int l = 0; l < NL; l += 4) {
            float4 q = *(const float4*)(p + l);
            if (q.x != 0.f) last = l;
            if (q.y != 0.f) last = l + 1;
            if (q.z != 0.f) last = l + 2;
            if (q.w != 0.f) last = l + 3;
        }
        int c = cnt[k * NU + u];
        if (c > 0) {
            v2 += (float)c;
            if (last >= 0) v1 += (float)(last - 1);
        }
    }
    g_v1[u] = v1; g_v2[u] = v2;
}

// ---------------- per-step spikes: JAX partitionable threefry ----------------
__global__ __launch_bounds__(256) void k_rng(const float* __restrict__ inp, int t) {
    int c = blockIdx.x * blockDim.x + threadIdx.x;
    if (c >= DIN) return;
    unsigned fk0, fk1;
    threefry(0u, 42u, 0u, (unsigned)t, fk0, fk1);   // fold_in(key(42), t)
    int r0 = blockIdx.y * 8;
    float sum = 0.f;
#pragma unroll
    for (int r = 0; r < 8; r++) {
        int i = (r0 + r) * DIN + c;           // logical index for PRNG counter
        unsigned o0, o1;
        threefry(fk0, fk1, 0u, (unsigned)i, o0, o1);
        unsigned b = o0 ^ o1;
        float u = __uint_as_float((b >> 9) | 0x3f800000u) - 1.0f;
        float x = inp[i] > u ? 1.0f : 0.0f;
        g_xq[(r0 + r) * DINP8 + c] = (signed char)(x != 0.f);
        sum += x;
    }
    atomicAdd(&g_xs[c], sum);
}

// ---------------- int8 IMMA GEMM1, 3-stage cp.async pipeline, K-chunk 128 ----------------
// C tile 64(M) x 128(N), 8 warps, warp tile 32x32. smem rows 128B, XOR-16B swizzle.
__device__ __forceinline__ void load_chunk(int gc, u32 aBase, u32 bBase,
                                           int mbc, int nbc, int tid) {
    int p = gc / 7;
    int off = (gc - p * 7) * 128;
    const signed char* wpl = g_wq + (long long)p * NH1 * DINP8;
#pragma unroll
    for (int i = 0; i < 2; i++) {
        int ch = i * 256 + tid;
        int row = ch >> 3, seg = ch & 7;
        u32 sw = (u32)(row * 128 + ((seg ^ (row & 7)) << 4));
        cpasync16(aBase + sw, &g_xq[(size_t)(mbc + row) * DINP8 + off + seg * 16]);
    }
#pragma unroll
    for (int i = 0; i < 4; i++) {
        int ch = i * 256 + tid;
        int row = ch >> 3, seg = ch & 7;
        u32 sw = (u32)(row * 128 + ((seg ^ (row & 7)) << 4));
        cpasync16(bBase + sw, &wpl[(size_t)(nbc + row) * DINP8 + off + seg * 16]);
    }
}

__global__ __launch_bounds__(256) void k_gemm1t(const float* __restrict__ b1) {
    extern __shared__ __align__(16) unsigned char dsm[];
    __shared__ float shs[128];

    int tid = threadIdx.x;
    int warp = tid >> 5, lane = tid & 31;
    int nbc = blockIdx.x * 128, mbc = blockIdx.y * 64;
    int wm = (warp >> 2) * 32, wn = (warp & 3) * 32;
    if (tid < 128) shs[tid] = 0.f;

    u32 smem0 = (u32)__cvta_generic_to_shared(dsm);
    u32 aB[3] = {smem0, smem0 + ABUF, smem0 + 2 * ABUF};
    u32 bB[3] = {smem0 + 3 * ABUF, smem0 + 3 * ABUF + BBUF, smem0 + 3 * ABUF + 2 * BBUF};

    int acc[3][2][4][4];
#pragma unroll
    for (int p = 0; p < 3; p++)
#pragma unroll
        for (int i = 0; i < 2; i++)
#pragma unroll
            for (int j = 0; j < 4; j++)
#pragma unroll
                for (int q = 0; q < 4; q++) acc[p][i][j][q] = 0;

    int arow0 = wm + (lane & 15);
    int akg   = lane >> 4;                                 // 0/1 -> 16B half of k32
    int brow0 = wn + (lane & 7) + ((lane >> 4) & 1) * 8;
    int bkg   = (lane >> 3) & 1;

    load_chunk(0, aB[0], bB[0], mbc, nbc, tid); cp_commit();
    load_chunk(1, aB[1], bB[1], mbc, nbc, tid); cp_commit();

    int buf = 0, gc = 0;
#pragma unroll
    for (int pl = 0; pl < 3; pl++) {
        for (int c7 = 0; c7 < 7; c7++) {
            cp_wait1();
            __syncthreads();
            if (gc + 2 < NCHUNK)
                load_chunk(gc + 2, aB[(gc + 2) % 3], bB[(gc + 2) % 3], mbc, nbc, tid);
            cp_commit();

            u32 aBase = aB[buf], bBase = bB[buf];
#pragma unroll
            for (int ks = 0; ks < 4; ks++) {      // each ks = K32 int8
                u32 a0, a1, a2, a3, a4, a5, a6, a7;
                u32 p0, p1, p2, p3, q0, q1, q2, q3;
                int segA = 2 * ks + akg;
                int rA0 = arow0, rA1 = arow0 + 16;
                ldm4(aBase + (u32)(rA0 * 128 + ((segA ^ (rA0 & 7)) << 4)), a0, a1, a2, a3);
                ldm4(aBase + (u32)(rA1 * 128 + ((segA ^ (rA1 & 7)) << 4)), a4, a5, a6, a7);
                int segB = 2 * ks + bkg;
                int rB0 = brow0, rB1 = brow0 + 16;
                ldm4(bBase + (u32)(rB0 * 128 + ((segB ^ (rB0 & 7)) << 4)), p0, p1, p2, p3);
                ldm4(bBase + (u32)(rB1 * 128 + ((segB ^ (rB1 & 7)) << 4)), q0, q1, q2, q3);

                imma16832(acc[pl][0][0][0], acc[pl][0][0][1], acc[pl][0][0][2], acc[pl][0][0][3], a0, a1, a2, a3, p0, p1);
                imma16832(acc[pl][0][1][0], acc[pl][0][1][1], acc[pl][0][1][2], acc[pl][0][1][3], a0, a1, a2, a3, p2, p3);
                imma16832(acc[pl][0][2][0], acc[pl][0][2][1], acc[pl][0][2][2], acc[pl][0][2][3], a0, a1, a2, a3, q0, q1);
                imma16832(acc[pl][0][3][0], acc[pl][0][3][1], acc[pl][0][3][2], acc[pl][0][3][3], a0, a1, a2, a3, q2, q3);
                imma16832(acc[pl][1][0][0], acc[pl][1][0][1], acc[pl][1][0][2], acc[pl][1][0][3], a4, a5, a6, a7, p0, p1);
                imma16832(acc[pl][1][1][0], acc[pl][1][1][1], acc[pl][1][1][2], acc[pl][1][1][3], a4, a5, a6, a7, p2, p3);
                imma16832(acc[pl][1][2][0], acc[pl][1][2][1], acc[pl][1][2][2], acc[pl][1][2][3], a4, a5, a6, a7, q0, q1);
                imma16832(acc[pl][1][3][0], acc[pl][1][3][1], acc[pl][1][3][2], acc[pl][1][3][3], a4, a5, a6, a7, q2, q3);
            }
            buf = (buf + 1) % 3;
            gc++;
        }
    }

    // ---------------- fused LIF epilogue (C frag mapping as verified) ----------------
    float s1 = g_sc[0], s2 = g_sc[1], s3 = g_sc[2];
    int r0 = lane >> 2, cp = (lane & 3) * 2;
    float csum[4][2];
#pragma unroll
    for (int j = 0; j < 4; j++) { csum[j][0] = 0.f; csum[j][1] = 0.f; }

#pragma unroll
    for (int j = 0; j < 4; j++) {
        int col = nbc + wn + j * 8 + cp;
        float2 bias = *(const float2*)&b1[col];
#pragma unroll
        for (int i = 0; i < 2; i++) {
#pragma unroll
            for (int h = 0; h < 2; h++) {
                int row = mbc + wm + i * 16 + r0 + h * 8;
                size_t idx = (size_t)row * NH1 + col;
                float2 om = *(float2*)&g_h1m[idx];
                float2 os = *(float2*)&g_h1s[idx];
                float g0 = fmaf(s1, (float)acc[0][i][j][2 * h + 0],
                           fmaf(s2, (float)acc[1][i][j][2 * h + 0],
                                s3 * (float)acc[2][i][j][2 * h + 0]));
                float g1 = fmaf(s1, (float)acc[0][i][j][2 * h + 1],
                           fmaf(s2, (float)acc[1][i][j][2 * h + 1],
                                s3 * (float)acc[2][i][j][2 * h + 1]));
                float v0 = g0 + bias.x + om.x * 0.2f * (1.f - os.x);
                float v1 = g1 + bias.y + om.y * 0.2f * (1.f - os.y);
                float sp0 = v0 > 0.5f ? 1.f : 0.f;
                float sp1 = v1 > 0.5f ? 1.f : 0.f;
                float2 vm = {v0, v1}, vs = {sp0, sp1};
                *(float2*)&g_h1m[idx] = vm;
                *(float2*)&g_h1s[idx] = vs;
                csum[j][0] += sp0; csum[j][1] += sp1;
            }
        }
    }
#pragma unroll
    for (int j = 0; j < 4; j++) {
        atomicAdd(&shs[wn + j * 8 + cp],     csum[j][0]);
        atomicAdd(&shs[wn + j * 8 + cp + 1], csum[j][1]);
    }
    __syncthreads();
    if (tid < 128) atomicAdd(&g_hs[nbc + tid], shs[tid]);
}

// ---------------- fused layer-2 LIF + scalar dots (one launch) ----------------
__global__ __launch_bounds__(256) void k_h2dot(const float* __restrict__ W2,
                                               const float* __restrict__ b2) {
    int tid = threadIdx.x;
    if (blockIdx.x < NB / 4) {
        int b0 = blockIdx.x * 4;
        float acc[4][10];
#pragma unroll
        for (int r = 0; r < 4; r++)
#pragma unroll
            for (int k = 0; k < 10; k++) acc[r][k] = 0.f;

        for (int j = tid; j < NH1; j += 256) {
            float w[10];
#pragma unroll
            for (int k = 0; k < 10; k++) w[k] = W2[k * NH1 + j];
#pragma unroll
            for (int r = 0; r < 4; r++) {
                float s = g_h1s[(size_t)(b0 + r) * NH1 + j];
#pragma unroll
                for (int k = 0; k < 10; k++) acc[r][k] += s * w[k];
            }
        }
#pragma unroll
        for (int r = 0; r < 4; r++)
#pragma unroll
            for (int k = 0; k < 10; k++)
#pragma unroll
                for (int o = 16; o; o >>= 1)
                    acc[r][k] += __shfl_down_sync(0xffffffffu, acc[r][k], o);

        __shared__ float sh[8][40];
        int lane = tid & 31, wrp = tid >> 5;
        if (lane == 0) {
#pragma unroll
            for (int r = 0; r < 4; r++)
#pragma unroll
                for (int k = 0; k < 10; k++) sh[wrp][r * 10 + k] = acc[r][k];
        }
        __syncthreads();
        if (tid < 40) {
            float v = 0.f;
#pragma unroll
            for (int w8 = 0; w8 < 8; w8++) v += sh[w8][tid];
            int r = tid / 10, k = tid % 10;
            int idx = (b0 + r) * NH2 + k;
            float m = g_h2m[idx] * 0.2f * (1.f - g_h2s[idx]) + v + b2[k];
            float s = m > 0.5f ? 1.f : 0.f;
            g_h2m[idx] = m; g_h2s[idx] = s; g_h2sum[idx] += s;
        }
    } else {
        float t1 = 0.f, t2 = 0.f, tc = 0.f;
        for (int u = tid; u < NU; u += 256) {
            float w = (u < DIN) ? g_xs[u] : g_hs[u - DIN];
            t1 += w * g_v1[u];
            t2 += w * g_v2[u];
            tc += w;
        }
        __shared__ float s1[256], s2[256], sc[256];
        s1[tid] = t1; s2[tid] = t2; sc[tid] = tc;
        __syncthreads();
        for (int o = 128; o; o >>= 1) {
            if (tid < o) { s1[tid] += s1[tid + o]; s2[tid] += s2[tid + o]; sc[tid] += sc[tid + o]; }
            __syncthreads();
        }
        if (tid == 0) { g_scal[0] += s1[0]; g_scal[1] += s2[0]; g_scal[2] += sc[0]; }
        __syncthreads();
        for (int u = tid; u < DIN; u += 256) g_xs[u] = 0.f;
        for (int u = tid; u < NH1; u += 256) g_hs[u] = 0.f;
    }
}

// ---------------- output: (h2sum/T, a1, a2, cs) ----------------
__global__ void k_out(float* __restrict__ out) {
    int i = blockIdx.x * blockDim.x + threadIdx.x;
    if (i < NB * NH2) out[i] = g_h2sum[i] / (float)TSTEPS;
    else if (i < NB * NH2 + 3) out[i] = g_scal[i - NB * NH2];
}

extern "C" void kernel_launch(void* const* d_in, const int* in_sizes, int n_in,
                              void* d_out, int out_size) {
    const float* inp = (const float*)d_in[0];
    const float* W1  = (const float*)d_in[1];
    const float* b1  = (const float*)d_in[2];
    const float* W2  = (const float*)d_in[3];
    const float* b2  = (const float*)d_in[4];
    const float* cmv = (const float*)d_in[5];
    const int*   cmc = (const int*)d_in[6];

    cudaFuncSetAttribute(k_gemm1t, cudaFuncAttributeMaxDynamicSharedMemorySize, DSMEM_SZ);

    k_init<<<2048, 256>>>();
    k_smax<<<512, 256>>>(W1);
    k_scale<<<1, 1>>>();
    k_split<<<(int)(((long long)NH1 * DINP8 + 255) / 256), 256>>>(W1);
    k_val<<<(NU + 255) / 256, 256>>>(cmv, cmc);

    for (int t = 0; t < TSTEPS; t++) {
        dim3 gr((DIN + 255) / 256, NB / 8);
        k_rng<<<gr, 256>>>(inp, t);
        dim3 g1(NH1 / 128, NB / 64);
        k_gemm1t<<<g1, 256, DSMEM_SZ>>>(b1);
        k_h2dot<<<NB / 4 + 1, 256>>>(W2, b2);
    }
    k_out<<<(NB * NH2 + 3 + 255) / 256, 256>>>((float*)d_out);
}

// round 9
// speedup vs baseline: 2.7588x; 2.7588x over previous
#include <cuda_runtime.h>
#include <cuda_fp16.h>
#include <cstdint>

typedef unsigned int u32;

#define NB    1024
#define DIN   784
#define DINP  832         // padded K per plane: 13 * 64
#define NH1   2048
#define NH2   10
#define NK    10
#define NU    2832        // DIN + NH1
#define NL    128
#define TSTEPS 20
#define NCHUNK 26         // 2 planes * 13 chunks of K=64
#define ABUF  8192        // 64 rows * 128B
#define BBUF  16384       // 128 rows * 128B
#define DSMEM_SZ (3 * (ABUF + BBUF))   // 73728

// ---------------- device state (no allocations allowed) ----------------
__device__ __align__(16) __half g_xh[2 * NB * DINP];      // spikes fp16 (0/1), double-buffered
__device__ __align__(16) __half g_wh[2 * NH1 * DINP];     // W1 2-plane fp16 split
__device__ float g_h1m[NB * NH1];
__device__ float g_h1s[NB * NH1];
__device__ float g_h2m[NB * NH2];
__device__ float g_h2s[NB * NH2];
__device__ float g_h2sum[NB * NH2];
__device__ float g_xs2[2 * DIN];     // double-buffered column sums of x
__device__ float g_hs[NH1];
__device__ float g_v1[NU];
__device__ float g_v2[NU];
__device__ float g_scal[3];   // a1, a2, cs

// ---------------- threefry2x32 (20 rounds), bit-exact vs JAX ----------------
__device__ __forceinline__ void threefry(unsigned k0, unsigned k1,
                                         unsigned x0, unsigned x1,
                                         unsigned& o0, unsigned& o1) {
    unsigned k2 = k0 ^ k1 ^ 0x1BD11BDAu;
    x0 += k0; x1 += k1;
#define RO(r) x0 += x1; x1 = __funnelshift_l(x1, x1, (r)); x1 ^= x0;
    RO(13) RO(15) RO(26) RO(6)   x0 += k1; x1 += k2 + 1u;
    RO(17) RO(29) RO(16) RO(24)  x0 += k2; x1 += k0 + 2u;
    RO(13) RO(15) RO(26) RO(6)   x0 += k0; x1 += k1 + 3u;
    RO(17) RO(29) RO(16) RO(24)  x0 += k1; x1 += k2 + 4u;
    RO(13) RO(15) RO(26) RO(6)   x0 += k2; x1 += k0 + 5u;
#undef RO
    o0 = x0; o1 = x1;
}

// ---------------- PTX wrappers ----------------
__device__ __forceinline__ void ldm4(u32 addr, u32& r0, u32& r1, u32& r2, u32& r3) {
    asm volatile("ldmatrix.sync.aligned.m8n8.x4.shared.b16 {%0,%1,%2,%3}, [%4];"
                 : "=r"(r0), "=r"(r1), "=r"(r2), "=r"(r3) : "r"(addr));
}
__device__ __forceinline__ void mma16816(float& c0, float& c1, float& c2, float& c3,
                                         u32 a0, u32 a1, u32 a2, u32 a3,
                                         u32 b0, u32 b1) {
    asm volatile("mma.sync.aligned.m16n8k16.row.col.f32.f16.f16.f32 "
                 "{%0,%1,%2,%3},{%4,%5,%6,%7},{%8,%9},{%0,%1,%2,%3};"
                 : "+f"(c0), "+f"(c1), "+f"(c2), "+f"(c3)
                 : "r"(a0), "r"(a1), "r"(a2), "r"(a3), "r"(b0), "r"(b1));
}
__device__ __forceinline__ void cpasync16(u32 dst, const void* src) {
    asm volatile("cp.async.cg.shared.global [%0], [%1], 16;" :: "r"(dst), "l"(src) : "memory");
}
__device__ __forceinline__ void cp_commit() {
    asm volatile("cp.async.commit_group;" ::: "memory");
}
__device__ __forceinline__ void cp_wait1() {
    asm volatile("cp.async.wait_group 1;" ::: "memory");
}

// ---------------- init: zero all persistent state ----------------
__global__ void k_init() {
    int stride = gridDim.x * blockDim.x;
    for (int idx = blockIdx.x * blockDim.x + threadIdx.x; idx < NB * NH1; idx += stride) {
        g_h1m[idx] = 0.f; g_h1s[idx] = 0.f;
        if (idx < 2 * NB * DINP) g_xh[idx] = __float2half(0.f);
        if (idx < NB * NH2) { g_h2m[idx] = 0.f; g_h2s[idx] = 0.f; g_h2sum[idx] = 0.f; }
        if (idx < 2 * DIN) g_xs2[idx] = 0.f;
        if (idx < NH1) g_hs[idx] = 0.f;
        if (idx < 3)   g_scal[idx] = 0.f;
    }
}

// ---------------- lossless-to-1e-8 2-plane fp16 split of W1 (K-padded) ----------------
__global__ void k_split(const float* __restrict__ W1) {
    int i = blockIdx.x * blockDim.x + threadIdx.x;
    if (i >= NH1 * DINP) return;
    int n = i / DINP, col = i - n * DINP;
    float w = (col < DIN) ? W1[n * DIN + col] : 0.f;
    __half h = __float2half_rn(w);
    float r = w - __half2float(h);
    g_wh[i] = h;
    g_wh[NH1 * DINP + i] = __float2half_rn(r);
}

// ---------------- precompute val1/val2 over core memory ----------------
__global__ void k_val(const float* __restrict__ vec, const int* __restrict__ cnt) {
    int u = blockIdx.x * blockDim.x + threadIdx.x;
    if (u >= NU) return;
    float v1 = 0.f, v2 = 0.f;
    for (int k = 0; k < NK; k++) {
        const float* p = vec + ((size_t)k * NU + u) * NL;
        int last = -1;
        for (int l = 0; l < NL; l += 4) {
            float4 q = *(const float4*)(p + l);
            if (q.x != 0.f) last = l;
            if (q.y != 0.f) last = l + 1;
            if (q.z != 0.f) last = l + 2;
            if (q.w != 0.f) last = l + 3;
        }
        int c = cnt[k * NU + u];
        if (c > 0) {
            v2 += (float)c;
            if (last >= 0) v1 += (float)(last - 1);
        }
    }
    g_v1[u] = v1; g_v2[u] = v2;
}

// ---------------- spike generation body (JAX partitionable threefry) ----------------
__device__ __forceinline__ void rng_body(const float* __restrict__ inp, int t,
                                         int bx, int by, int tid) {
    int c = bx * 256 + tid;
    if (c >= DIN) return;
    unsigned fk0, fk1;
    threefry(0u, 42u, 0u, (unsigned)t, fk0, fk1);   // fold_in(key(42), t)
    int par = t & 1;
    __half* xh = g_xh + (size_t)par * NB * DINP;
    int r0 = by * 8;
    float sum = 0.f;
#pragma unroll
    for (int r = 0; r < 8; r++) {
        int i = (r0 + r) * DIN + c;           // logical index for PRNG counter
        unsigned o0, o1;
        threefry(fk0, fk1, 0u, (unsigned)i, o0, o1);
        unsigned b = o0 ^ o1;
        float u = __uint_as_float((b >> 9) | 0x3f800000u) - 1.0f;
        float x = inp[i] > u ? 1.0f : 0.0f;
        xh[(r0 + r) * DINP + c] = __float2half(x);
        sum += x;
    }
    atomicAdd(&g_xs2[par * DIN + c], sum);
}

__global__ __launch_bounds__(256) void k_rng(const float* __restrict__ inp, int t) {
    rng_body(inp, t, blockIdx.x, blockIdx.y, threadIdx.x);
}

// ---------------- fp16 mma GEMM1, 3-stage cp.async pipeline, K-tile 64 ----------------
__device__ __forceinline__ void load_chunk(int gc, u32 aBase, u32 bBase,
                                           int mbc, int nbc, int tid,
                                           const __half* __restrict__ xh) {
    int p = gc / 13;
    int off = (gc - p * 13) * 64;
    const __half* wpl = g_wh + (size_t)p * NH1 * DINP;
#pragma unroll
    for (int i = 0; i < 2; i++) {
        int ch = i * 256 + tid;
        int row = ch >> 3, seg = ch & 7;
        u32 sw = (u32)(row * 128 + ((seg ^ (row & 7)) << 4));
        cpasync16(aBase + sw, &xh[(size_t)(mbc + row) * DINP + off + seg * 8]);
    }
#pragma unroll
    for (int i = 0; i < 4; i++) {
        int ch = i * 256 + tid;
        int row = ch >> 3, seg = ch & 7;
        u32 sw = (u32)(row * 128 + ((seg ^ (row & 7)) << 4));
        cpasync16(bBase + sw, &wpl[(size_t)(nbc + row) * DINP + off + seg * 8]);
    }
}

__global__ __launch_bounds__(256) void k_gemm1t(const float* __restrict__ b1, int par) {
    extern __shared__ __align__(16) unsigned char dsm[];
    __shared__ float shs[128];

    int tid = threadIdx.x;
    int warp = tid >> 5, lane = tid & 31;
    int nbc = blockIdx.x * 128, mbc = blockIdx.y * 64;
    int wm = (warp >> 2) * 32, wn = (warp & 3) * 32;
    if (tid < 128) shs[tid] = 0.f;
    const __half* xh = g_xh + (size_t)par * NB * DINP;

    u32 smem0 = (u32)__cvta_generic_to_shared(dsm);
    u32 aB[3] = {smem0, smem0 + ABUF, smem0 + 2 * ABUF};
    u32 bB[3] = {smem0 + 3 * ABUF, smem0 + 3 * ABUF + BBUF, smem0 + 3 * ABUF + 2 * BBUF};

    float acc[2][4][4];
#pragma unroll
    for (int i = 0; i < 2; i++)
#pragma unroll
        for (int j = 0; j < 4; j++)
#pragma unroll
            for (int q = 0; q < 4; q++) acc[i][j][q] = 0.f;

    int arow0 = wm + (lane & 15);
    int akg   = lane >> 4;
    int brow0 = wn + (lane & 7) + ((lane >> 4) & 1) * 8;
    int bkg   = (lane >> 3) & 1;

    load_chunk(0, aB[0], bB[0], mbc, nbc, tid, xh); cp_commit();
    load_chunk(1, aB[1], bB[1], mbc, nbc, tid, xh); cp_commit();

    int buf = 0;
    for (int c = 0; c < NCHUNK; c++) {
        cp_wait1();
        __syncthreads();
        if (c + 2 < NCHUNK)
            load_chunk(c + 2, aB[(c + 2) % 3], bB[(c + 2) % 3], mbc, nbc, tid, xh);
        cp_commit();

        u32 aBase = aB[buf], bBase = bB[buf];
#pragma unroll
        for (int ks = 0; ks < 4; ks++) {
            u32 a0, a1, a2, a3, a4, a5, a6, a7;
            u32 p0, p1, p2, p3, q0, q1, q2, q3;
            int segA = 2 * ks + akg;
            int rA0 = arow0, rA1 = arow0 + 16;
            ldm4(aBase + (u32)(rA0 * 128 + ((segA ^ (rA0 & 7)) << 4)), a0, a1, a2, a3);
            ldm4(aBase + (u32)(rA1 * 128 + ((segA ^ (rA1 & 7)) << 4)), a4, a5, a6, a7);
            int segB = 2 * ks + bkg;
            int rB0 = brow0, rB1 = brow0 + 16;
            ldm4(bBase + (u32)(rB0 * 128 + ((segB ^ (rB0 & 7)) << 4)), p0, p1, p2, p3);
            ldm4(bBase + (u32)(rB1 * 128 + ((segB ^ (rB1 & 7)) << 4)), q0, q1, q2, q3);

            mma16816(acc[0][0][0], acc[0][0][1], acc[0][0][2], acc[0][0][3], a0, a1, a2, a3, p0, p1);
            mma16816(acc[0][1][0], acc[0][1][1], acc[0][1][2], acc[0][1][3], a0, a1, a2, a3, p2, p3);
            mma16816(acc[0][2][0], acc[0][2][1], acc[0][2][2], acc[0][2][3], a0, a1, a2, a3, q0, q1);
            mma16816(acc[0][3][0], acc[0][3][1], acc[0][3][2], acc[0][3][3], a0, a1, a2, a3, q2, q3);
            mma16816(acc[1][0][0], acc[1][0][1], acc[1][0][2], acc[1][0][3], a4, a5, a6, a7, p0, p1);
            mma16816(acc[1][1][0], acc[1][1][1], acc[1][1][2], acc[1][1][3], a4, a5, a6, a7, p2, p3);
            mma16816(acc[1][2][0], acc[1][2][1], acc[1][2][2], acc[1][2][3], a4, a5, a6, a7, q0, q1);
            mma16816(acc[1][3][0], acc[1][3][1], acc[1][3][2], acc[1][3][3], a4, a5, a6, a7, q2, q3);
        }
        buf = (buf + 1) % 3;
    }

    // ---------------- fused LIF epilogue (verified fragment mapping) ----------------
    int r0 = lane >> 2, cp = (lane & 3) * 2;
    float csum[4][2];
#pragma unroll
    for (int j = 0; j < 4; j++) { csum[j][0] = 0.f; csum[j][1] = 0.f; }

#pragma unroll
    for (int j = 0; j < 4; j++) {
        int col = nbc + wn + j * 8 + cp;
        float2 bias = *(const float2*)&b1[col];
#pragma unroll
        for (int i = 0; i < 2; i++) {
#pragma unroll
            for (int h = 0; h < 2; h++) {
                int row = mbc + wm + i * 16 + r0 + h * 8;
                size_t idx = (size_t)row * NH1 + col;
                float2 om = *(float2*)&g_h1m[idx];
                float2 os = *(float2*)&g_h1s[idx];
                float v0 = acc[i][j][2 * h + 0] + bias.x + om.x * 0.2f * (1.f - os.x);
                float v1 = acc[i][j][2 * h + 1] + bias.y + om.y * 0.2f * (1.f - os.y);
                float s0 = v0 > 0.5f ? 1.f : 0.f;
                float s1 = v1 > 0.5f ? 1.f : 0.f;
                float2 vm = {v0, v1}, vs = {s0, s1};
                *(float2*)&g_h1m[idx] = vm;
                *(float2*)&g_h1s[idx] = vs;
                csum[j][0] += s0; csum[j][1] += s1;
            }
        }
    }
#pragma unroll
    for (int j = 0; j < 4; j++) {
        atomicAdd(&shs[wn + j * 8 + cp],     csum[j][0]);
        atomicAdd(&shs[wn + j * 8 + cp + 1], csum[j][1]);
    }
    __syncthreads();
    if (tid < 128) atomicAdd(&g_hs[nbc + tid], shs[tid]);
}

// ---------------- fused: layer-2 LIF + scalar dots (step t)  ∥  rng (step t+1) ----------------
// blocks [0,256): h2 update; block 256: dots + zero xs[t&1]/hs; blocks [257,769): rng(t+1)
__global__ __launch_bounds__(256) void k_post(const float* __restrict__ inp,
                                              const float* __restrict__ W2,
                                              const float* __restrict__ b2, int t) {
    int tid = threadIdx.x;
    int bid = blockIdx.x;
    if (bid >= 257) {
        if (t + 1 >= TSTEPS) return;
        int rb = bid - 257;
        rng_body(inp, t + 1, rb & 3, rb >> 2, tid);
        return;
    }
    if (bid < 256) {
        int b0 = bid * 4;
        float acc[4][10];
#pragma unroll
        for (int r = 0; r < 4; r++)
#pragma unroll
            for (int k = 0; k < 10; k++) acc[r][k] = 0.f;

        for (int j = tid; j < NH1; j += 256) {
            float w[10];
#pragma unroll
            for (int k = 0; k < 10; k++) w[k] = W2[k * NH1 + j];
#pragma unroll
            for (int r = 0; r < 4; r++) {
                float s = g_h1s[(size_t)(b0 + r) * NH1 + j];
#pragma unroll
                for (int k = 0; k < 10; k++) acc[r][k] += s * w[k];
            }
        }
#pragma unroll
        for (int r = 0; r < 4; r++)
#pragma unroll
            for (int k = 0; k < 10; k++)
#pragma unroll
                for (int o = 16; o; o >>= 1)
                    acc[r][k] += __shfl_down_sync(0xffffffffu, acc[r][k], o);

        __shared__ float sh[8][40];
        int lane = tid & 31, wrp = tid >> 5;
        if (lane == 0) {
#pragma unroll
            for (int r = 0; r < 4; r++)
#pragma unroll
                for (int k = 0; k < 10; k++) sh[wrp][r * 10 + k] = acc[r][k];
        }
        __syncthreads();
        if (tid < 40) {
            float v = 0.f;
#pragma unroll
            for (int w8 = 0; w8 < 8; w8++) v += sh[w8][tid];
            int r = tid / 10, k = tid % 10;
            int idx = (b0 + r) * NH2 + k;
            float m = g_h2m[idx] * 0.2f * (1.f - g_h2s[idx]) + v + b2[k];
            float s = m > 0.5f ? 1.f : 0.f;
            g_h2m[idx] = m; g_h2s[idx] = s; g_h2sum[idx] += s;
        }
    } else {
        // dots over (xs[t&1], hs) + zero both for reuse
        const float* xs = g_xs2 + (t & 1) * DIN;
        float t1 = 0.f, t2 = 0.f, tc = 0.f;
        for (int u = tid; u < NU; u += 256) {
            float w = (u < DIN) ? xs[u] : g_hs[u - DIN];
            t1 += w * g_v1[u];
            t2 += w * g_v2[u];
            tc += w;
        }
        __shared__ float s1[256], s2[256], sc[256];
        s1[tid] = t1; s2[tid] = t2; sc[tid] = tc;
        __syncthreads();
        for (int o = 128; o; o >>= 1) {
            if (tid < o) { s1[tid] += s1[tid + o]; s2[tid] += s2[tid + o]; sc[tid] += sc[tid + o]; }
            __syncthreads();
        }
        if (tid == 0) { g_scal[0] += s1[0]; g_scal[1] += s2[0]; g_scal[2] += sc[0]; }
        __syncthreads();
        for (int u = tid; u < DIN; u += 256) g_xs2[(t & 1) * DIN + u] = 0.f;
        for (int u = tid; u < NH1; u += 256) g_hs[u] = 0.f;
    }
}

// ---------------- output: (h2sum/T, a1, a2, cs) ----------------
__global__ void k_out(float* __restrict__ out) {
    int i = blockIdx.x * blockDim.x + threadIdx.x;
    if (i < NB * NH2) out[i] = g_h2sum[i] / (float)TSTEPS;
    else if (i < NB * NH2 + 3) out[i] = g_scal[i - NB * NH2];
}

extern "C" void kernel_launch(void* const* d_in, const int* in_sizes, int n_in,
                              void* d_out, int out_size) {
    const float* inp = (const float*)d_in[0];
    const float* W1  = (const float*)d_in[1];
    const float* b1  = (const float*)d_in[2];
    const float* W2  = (const float*)d_in[3];
    const float* b2  = (const float*)d_in[4];
    const float* cmv = (const float*)d_in[5];
    const int*   cmc = (const int*)d_in[6];

    cudaFuncSetAttribute(k_gemm1t, cudaFuncAttributeMaxDynamicSharedMemorySize, DSMEM_SZ);

    k_init<<<2048, 256>>>();
    k_split<<<(NH1 * DINP + 255) / 256, 256>>>(W1);
    k_val<<<(NU + 255) / 256, 256>>>(cmv, cmc);

    k_rng<<<dim3(4, 128), 256>>>(inp, 0);
    for (int t = 0; t < TSTEPS; t++) {
        dim3 g1(NH1 / 128, NB / 64);
        k_gemm1t<<<g1, 256, DSMEM_SZ>>>(b1, t & 1);
        k_post<<<769, 256>>>(inp, W2, b2, t);
    }
    k_out<<<(NB * NH2 + 3 + 255) / 256, 256>>>((float*)d_out);
}